// round 10
// baseline (speedup 1.0000x reference)
#include <cuda_runtime.h>

#define BATCH 4096
#define SEQ   200
#define EMB   128
#define VOCAB 100000

// Scratch: P[v] = { emb[v]·W0, emb[v]·W1 }  (recomputed every launch)
__device__ __align__(16) float Pbuf[VOCAB * 2];

// ---- Kernel 1: P = embeddings @ W^T.  8 lanes per row, 8 rows per warp. ----
__global__ __launch_bounds__(256)
void precompute_kernel(const float* __restrict__ emb,
                       const float* __restrict__ W)
{
    const int warp_g = (blockIdx.x * blockDim.x + threadIdx.x) >> 5;
    const int lane   = threadIdx.x & 31;
    const int sub    = lane & 7;
    const int grp    = lane >> 3;

    const int row_base = warp_g * 8;
    if (row_base >= VOCAB) return;

    const float4* emb4 = reinterpret_cast<const float4*>(emb);
    const float4* W4   = reinterpret_cast<const float4*>(W);

    float4 w0[4], w1[4];
    #pragma unroll
    for (int i = 0; i < 4; i++) {
        w0[i] = __ldg(&W4[sub + 8 * i]);
        w1[i] = __ldg(&W4[32 + sub + 8 * i]);
    }

    int rA = row_base + grp;
    int rB = row_base + 4 + grp;
    int cA = (rA < VOCAB) ? rA : VOCAB - 1;
    int cB = (rB < VOCAB) ? rB : VOCAB - 1;

    float4 eA[4], eB[4];
    #pragma unroll
    for (int i = 0; i < 4; i++) {
        eA[i] = __ldg(&emb4[cA * 32 + sub + 8 * i]);
        eB[i] = __ldg(&emb4[cB * 32 + sub + 8 * i]);
    }

    float dA0 = 0.f, dA1 = 0.f, dB0 = 0.f, dB1 = 0.f;
    #pragma unroll
    for (int i = 0; i < 4; i++) {
        dA0 += eA[i].x * w0[i].x + eA[i].y * w0[i].y + eA[i].z * w0[i].z + eA[i].w * w0[i].w;
        dA1 += eA[i].x * w1[i].x + eA[i].y * w1[i].y + eA[i].z * w1[i].z + eA[i].w * w1[i].w;
        dB0 += eB[i].x * w0[i].x + eB[i].y * w0[i].y + eB[i].z * w0[i].z + eB[i].w * w0[i].w;
        dB1 += eB[i].x * w1[i].x + eB[i].y * w1[i].y + eB[i].z * w1[i].z + eB[i].w * w1[i].w;
    }

    #pragma unroll
    for (int off = 4; off > 0; off >>= 1) {
        dA0 += __shfl_xor_sync(0xFFFFFFFFu, dA0, off);
        dA1 += __shfl_xor_sync(0xFFFFFFFFu, dA1, off);
        dB0 += __shfl_xor_sync(0xFFFFFFFFu, dB0, off);
        dB1 += __shfl_xor_sync(0xFFFFFFFFu, dB1, off);
    }

    if (sub == 0) {
        float2* P2 = reinterpret_cast<float2*>(Pbuf);
        if (rA < VOCAB) P2[rA] = make_float2(dA0, dA1);
        if (rB < VOCAB) P2[rB] = make_float2(dB0, dB1);
    }
}

// ---- Kernel 2: masked mean over P + bias.  4 warps per row (50 tokens each). ----
__global__ __launch_bounds__(128)
void pool_kernel(const int* __restrict__ x,
                 const float* __restrict__ bias,
                 float* __restrict__ out)
{
    const int tid  = threadIdx.x;
    const int warp = tid >> 5;              // quarter 0..3
    const int lane = tid & 31;
    const int row  = blockIdx.x;

    const int* xr = x + row * SEQ + warp * 50;
    const float2* P = reinterpret_cast<const float2*>(Pbuf);

    // 50 tokens per warp: 1 full coalesced load + 18-lane tail. Short 2-gather chain.
    int idx0 = __ldg(&xr[lane]);
    int idx1 = (lane + 32 < 50) ? __ldg(&xr[lane + 32]) : -1;

    float m0 = (idx0 >= 0) ? 1.f : 0.f;
    float m1 = (idx1 >= 0) ? 1.f : 0.f;
    int   c0 = (idx0 >= 0) ? idx0 : 0;      // padding -> row 0 (broadcast, L1-hit)
    int   c1 = (idx1 >= 0) ? idx1 : 0;

    float2 p0 = __ldg(&P[c0]);              // two independent gathers in flight
    float2 p1 = __ldg(&P[c1]);

    float a0 = fmaf(m0, p0.x, m1 * p1.x);
    float a1 = fmaf(m0, p0.y, m1 * p1.y);
    float c  = m0 + m1;

    #pragma unroll
    for (int off = 16; off > 0; off >>= 1) {
        a0 += __shfl_xor_sync(0xFFFFFFFFu, a0, off);
        a1 += __shfl_xor_sync(0xFFFFFFFFu, a1, off);
        c  += __shfl_xor_sync(0xFFFFFFFFu, c,  off);
    }

    __shared__ __align__(16) float4 part[4];
    if (lane == 0) part[warp] = make_float4(a0, a1, c, 0.f);
    __syncthreads();

    if (tid == 0) {
        float s0 = part[0].x + part[1].x + part[2].x + part[3].x;
        float s1 = part[0].y + part[1].y + part[2].y + part[3].y;
        float cn = part[0].z + part[1].z + part[2].z + part[3].z;  // >= 1
        float inv = 1.0f / cn;
        out[row * 2 + 0] = s0 * inv + bias[0];
        out[row * 2 + 1] = s1 * inv + bias[1];
    }
}

extern "C" void kernel_launch(void* const* d_in, const int* in_sizes, int n_in,
                              void* d_out, int out_size)
{
    const int* x     = (const int*)d_in[0];       // int32 [4096,200]
    const float* emb = (const float*)d_in[1];     // [100000,128]
    const float* W   = (const float*)d_in[2];     // [2,128]
    const float* b   = (const float*)d_in[3];     // [2]
    float* out       = (float*)d_out;             // [4096,2]

    precompute_kernel<<<(VOCAB + 63) / 64, 256>>>(emb, W);
    pool_kernel<<<BATCH, 128>>>(x, b, out);       // 1 row per 128-thread block
}

// round 11
// speedup vs baseline: 1.1376x; 1.1376x over previous
#include <cuda_runtime.h>

#define BATCH 4096
#define SEQ   200
#define EMB   128
#define VOCAB 100000

// Scratch: P[v] = { emb[v]·W0, emb[v]·W1 }  (recomputed every launch)
__device__ __align__(16) float Pbuf[VOCAB * 2];

// ---- Kernel 1: P = embeddings @ W^T.  8 lanes per row, 8 rows per warp. ----
__global__ __launch_bounds__(256)
void precompute_kernel(const float* __restrict__ emb,
                       const float* __restrict__ W)
{
    const int warp_g = (blockIdx.x * blockDim.x + threadIdx.x) >> 5;
    const int lane   = threadIdx.x & 31;
    const int sub    = lane & 7;
    const int grp    = lane >> 3;

    const int row_base = warp_g * 8;
    if (row_base >= VOCAB) return;

    const float4* emb4 = reinterpret_cast<const float4*>(emb);
    const float4* W4   = reinterpret_cast<const float4*>(W);

    float4 w0[4], w1[4];
    #pragma unroll
    for (int i = 0; i < 4; i++) {
        w0[i] = __ldg(&W4[sub + 8 * i]);
        w1[i] = __ldg(&W4[32 + sub + 8 * i]);
    }

    int rA = row_base + grp;
    int rB = row_base + 4 + grp;
    int cA = (rA < VOCAB) ? rA : VOCAB - 1;
    int cB = (rB < VOCAB) ? rB : VOCAB - 1;

    float4 eA[4], eB[4];
    #pragma unroll
    for (int i = 0; i < 4; i++) {
        eA[i] = __ldg(&emb4[cA * 32 + sub + 8 * i]);
        eB[i] = __ldg(&emb4[cB * 32 + sub + 8 * i]);
    }

    float dA0 = 0.f, dA1 = 0.f, dB0 = 0.f, dB1 = 0.f;
    #pragma unroll
    for (int i = 0; i < 4; i++) {
        dA0 += eA[i].x * w0[i].x + eA[i].y * w0[i].y + eA[i].z * w0[i].z + eA[i].w * w0[i].w;
        dA1 += eA[i].x * w1[i].x + eA[i].y * w1[i].y + eA[i].z * w1[i].z + eA[i].w * w1[i].w;
        dB0 += eB[i].x * w0[i].x + eB[i].y * w0[i].y + eB[i].z * w0[i].z + eB[i].w * w0[i].w;
        dB1 += eB[i].x * w1[i].x + eB[i].y * w1[i].y + eB[i].z * w1[i].z + eB[i].w * w1[i].w;
    }

    #pragma unroll
    for (int off = 4; off > 0; off >>= 1) {
        dA0 += __shfl_xor_sync(0xFFFFFFFFu, dA0, off);
        dA1 += __shfl_xor_sync(0xFFFFFFFFu, dA1, off);
        dB0 += __shfl_xor_sync(0xFFFFFFFFu, dB0, off);
        dB1 += __shfl_xor_sync(0xFFFFFFFFu, dB1, off);
    }

    if (sub == 0) {
        float2* P2 = reinterpret_cast<float2*>(Pbuf);
        if (rA < VOCAB) P2[rA] = make_float2(dA0, dA1);
        if (rB < VOCAB) P2[rB] = make_float2(dB0, dB1);
    }
}

// ---- Kernel 2: masked mean over P + bias. 2 warps/row, int4 index loads. ----
// Half-row = 100 tokens = 25 int4 (16B-aligned: 100 ints * 4B = 400B offset).
// Lane < 25 loads ONE int4 (4 tokens) then issues 4 independent 8B gathers.
__global__ __launch_bounds__(256)
void pool_kernel(const int* __restrict__ x,
                 const float* __restrict__ bias,
                 float* __restrict__ out)
{
    const int tid    = threadIdx.x;
    const int warp   = tid >> 5;            // 0..7
    const int lane   = tid & 31;
    const int warp_g = blockIdx.x * 8 + warp;
    const int row    = warp_g >> 1;         // 4 rows per block
    const int half   = warp_g & 1;

    const int4* xq = reinterpret_cast<const int4*>(x + row * SEQ + half * 100);
    const float2* P = reinterpret_cast<const float2*>(Pbuf);

    // One 16B index load per lane (lanes 0..24), covering 4 tokens.
    int4 q = (lane < 25) ? __ldg(&xq[lane]) : make_int4(-1, -1, -1, -1);

    int   i0 = q.x, i1 = q.y, i2 = q.z, i3 = q.w;
    float m0 = (i0 >= 0) ? 1.f : 0.f;
    float m1 = (i1 >= 0) ? 1.f : 0.f;
    float m2 = (i2 >= 0) ? 1.f : 0.f;
    float m3 = (i3 >= 0) ? 1.f : 0.f;
    int   c0 = (i0 >= 0) ? i0 : 0;          // padding -> row 0 (broadcast, L1-hit)
    int   c1 = (i1 >= 0) ? i1 : 0;
    int   c2 = (i2 >= 0) ? i2 : 0;
    int   c3 = (i3 >= 0) ? i3 : 0;

    // 4 independent gathers in flight (MLP=4).
    float2 p0 = __ldg(&P[c0]);
    float2 p1 = __ldg(&P[c1]);
    float2 p2 = __ldg(&P[c2]);
    float2 p3 = __ldg(&P[c3]);

    float a0 = m0 * p0.x + m1 * p1.x + m2 * p2.x + m3 * p3.x;
    float a1 = m0 * p0.y + m1 * p1.y + m2 * p2.y + m3 * p3.y;
    float c  = m0 + m1 + m2 + m3;

    #pragma unroll
    for (int off = 16; off > 0; off >>= 1) {
        a0 += __shfl_xor_sync(0xFFFFFFFFu, a0, off);
        a1 += __shfl_xor_sync(0xFFFFFFFFu, a1, off);
        c  += __shfl_xor_sync(0xFFFFFFFFu, c,  off);
    }

    __shared__ __align__(16) float4 part[8];
    if (lane == 0) part[warp] = make_float4(a0, a1, c, 0.f);
    __syncthreads();

    // 4 rows per block: thread t < 4 combines the two halves of row blockIdx.x*4+t.
    if (tid < 4) {
        float4 h0 = part[2 * tid];
        float4 h1 = part[2 * tid + 1];
        float s0 = h0.x + h1.x;
        float s1 = h0.y + h1.y;
        float cn = h0.z + h1.z;              // >= 1 (column 0 always valid)
        float inv = 1.0f / cn;
        int r = blockIdx.x * 4 + tid;
        out[r * 2 + 0] = s0 * inv + bias[0];
        out[r * 2 + 1] = s1 * inv + bias[1];
    }
}

extern "C" void kernel_launch(void* const* d_in, const int* in_sizes, int n_in,
                              void* d_out, int out_size)
{
    const int* x     = (const int*)d_in[0];       // int32 [4096,200]
    const float* emb = (const float*)d_in[1];     // [100000,128]
    const float* W   = (const float*)d_in[2];     // [2,128]
    const float* b   = (const float*)d_in[3];     // [2]
    float* out       = (float*)d_out;             // [4096,2]

    precompute_kernel<<<(VOCAB + 63) / 64, 256>>>(emb, W);
    pool_kernel<<<BATCH / 4, 256>>>(x, b, out);   // 1024 blocks, 2 warps per row
}

// round 12
// speedup vs baseline: 1.1575x; 1.0175x over previous
#include <cuda_runtime.h>

#define BATCH 4096
#define SEQ   200
#define EMB   128
#define VOCAB 100000

// Scratch: P[v] = { emb[v]·W0, emb[v]·W1 }  (recomputed every launch)
__device__ __align__(16) float Pbuf[VOCAB * 2];

// ---- Kernel 1: P = embeddings @ W^T.  8 lanes per row, 8 rows per warp. ----
__global__ __launch_bounds__(256)
void precompute_kernel(const float* __restrict__ emb,
                       const float* __restrict__ W)
{
    const int warp_g = (blockIdx.x * blockDim.x + threadIdx.x) >> 5;
    const int lane   = threadIdx.x & 31;
    const int sub    = lane & 7;
    const int grp    = lane >> 3;

    const int row_base = warp_g * 8;
    if (row_base >= VOCAB) return;

    const float4* emb4 = reinterpret_cast<const float4*>(emb);
    const float4* W4   = reinterpret_cast<const float4*>(W);

    float4 w0[4], w1[4];
    #pragma unroll
    for (int i = 0; i < 4; i++) {
        w0[i] = __ldg(&W4[sub + 8 * i]);
        w1[i] = __ldg(&W4[32 + sub + 8 * i]);
    }

    int rA = row_base + grp;
    int rB = row_base + 4 + grp;
    int cA = (rA < VOCAB) ? rA : VOCAB - 1;
    int cB = (rB < VOCAB) ? rB : VOCAB - 1;

    float4 eA[4], eB[4];
    #pragma unroll
    for (int i = 0; i < 4; i++) {
        eA[i] = __ldg(&emb4[cA * 32 + sub + 8 * i]);
        eB[i] = __ldg(&emb4[cB * 32 + sub + 8 * i]);
    }

    float dA0 = 0.f, dA1 = 0.f, dB0 = 0.f, dB1 = 0.f;
    #pragma unroll
    for (int i = 0; i < 4; i++) {
        dA0 += eA[i].x * w0[i].x + eA[i].y * w0[i].y + eA[i].z * w0[i].z + eA[i].w * w0[i].w;
        dA1 += eA[i].x * w1[i].x + eA[i].y * w1[i].y + eA[i].z * w1[i].z + eA[i].w * w1[i].w;
        dB0 += eB[i].x * w0[i].x + eB[i].y * w0[i].y + eB[i].z * w0[i].z + eB[i].w * w0[i].w;
        dB1 += eB[i].x * w1[i].x + eB[i].y * w1[i].y + eB[i].z * w1[i].z + eB[i].w * w1[i].w;
    }

    #pragma unroll
    for (int off = 4; off > 0; off >>= 1) {
        dA0 += __shfl_xor_sync(0xFFFFFFFFu, dA0, off);
        dA1 += __shfl_xor_sync(0xFFFFFFFFu, dA1, off);
        dB0 += __shfl_xor_sync(0xFFFFFFFFu, dB0, off);
        dB1 += __shfl_xor_sync(0xFFFFFFFFu, dB1, off);
    }

    if (sub == 0) {
        float2* P2 = reinterpret_cast<float2*>(Pbuf);
        if (rA < VOCAB) P2[rA] = make_float2(dA0, dA1);
        if (rB < VOCAB) P2[rB] = make_float2(dB0, dB1);
    }
}

// ---- Kernel 2: masked mean over P + bias. 512-thr CTAs (low oe -> low L1tex spread). ----
// 16 warps/block, 2 warps per row => 8 rows per block, grid 512 (oe ~3.5 per SM).
__global__ __launch_bounds__(512)
void pool_kernel(const int* __restrict__ x,
                 const float* __restrict__ bias,
                 float* __restrict__ out)
{
    const int tid    = threadIdx.x;
    const int warp   = tid >> 5;            // 0..15
    const int lane   = tid & 31;
    const int warp_g = blockIdx.x * 16 + warp;
    const int row    = warp_g >> 1;         // 8 rows per block
    const int half   = warp_g & 1;

    const int4* xq = reinterpret_cast<const int4*>(x + row * SEQ + half * 100);
    const float2* P = reinterpret_cast<const float2*>(Pbuf);

    // One 16B index load per lane (lanes 0..24), covering 4 tokens.
    int4 q = (lane < 25) ? __ldg(&xq[lane]) : make_int4(-1, -1, -1, -1);

    int   i0 = q.x, i1 = q.y, i2 = q.z, i3 = q.w;
    float m0 = (i0 >= 0) ? 1.f : 0.f;
    float m1 = (i1 >= 0) ? 1.f : 0.f;
    float m2 = (i2 >= 0) ? 1.f : 0.f;
    float m3 = (i3 >= 0) ? 1.f : 0.f;
    int   c0 = (i0 >= 0) ? i0 : 0;          // padding -> row 0 (broadcast, L1-hit)
    int   c1 = (i1 >= 0) ? i1 : 0;
    int   c2 = (i2 >= 0) ? i2 : 0;
    int   c3 = (i3 >= 0) ? i3 : 0;

    // 4 independent gathers in flight (MLP=4).
    float2 p0 = __ldg(&P[c0]);
    float2 p1 = __ldg(&P[c1]);
    float2 p2 = __ldg(&P[c2]);
    float2 p3 = __ldg(&P[c3]);

    float a0 = m0 * p0.x + m1 * p1.x + m2 * p2.x + m3 * p3.x;
    float a1 = m0 * p0.y + m1 * p1.y + m2 * p2.y + m3 * p3.y;
    float c  = m0 + m1 + m2 + m3;

    #pragma unroll
    for (int off = 16; off > 0; off >>= 1) {
        a0 += __shfl_xor_sync(0xFFFFFFFFu, a0, off);
        a1 += __shfl_xor_sync(0xFFFFFFFFu, a1, off);
        c  += __shfl_xor_sync(0xFFFFFFFFu, c,  off);
    }

    __shared__ __align__(16) float4 part[16];
    if (lane == 0) part[warp] = make_float4(a0, a1, c, 0.f);
    __syncthreads();

    // 8 rows per block: thread t < 8 combines the two halves of row blockIdx.x*8+t.
    if (tid < 8) {
        float4 h0 = part[2 * tid];
        float4 h1 = part[2 * tid + 1];
        float s0 = h0.x + h1.x;
        float s1 = h0.y + h1.y;
        float cn = h0.z + h1.z;              // >= 1 (column 0 always valid)
        float inv = 1.0f / cn;
        int r = blockIdx.x * 8 + tid;
        out[r * 2 + 0] = s0 * inv + bias[0];
        out[r * 2 + 1] = s1 * inv + bias[1];
    }
}

extern "C" void kernel_launch(void* const* d_in, const int* in_sizes, int n_in,
                              void* d_out, int out_size)
{
    const int* x     = (const int*)d_in[0];       // int32 [4096,200]
    const float* emb = (const float*)d_in[1];     // [100000,128]
    const float* W   = (const float*)d_in[2];     // [2,128]
    const float* b   = (const float*)d_in[3];     // [2]
    float* out       = (float*)d_out;             // [4096,2]

    precompute_kernel<<<(VOCAB + 63) / 64, 256>>>(emb, W);
    pool_kernel<<<BATCH / 8, 512>>>(x, b, out);   // 512 blocks x 512 threads
}

// round 13
// speedup vs baseline: 1.1604x; 1.0025x over previous
#include <cuda_runtime.h>

#define BATCH 4096
#define SEQ   200
#define EMB   128
#define VOCAB 100000
#define NPRE  1563            // ceil(100000 / 64) precompute blocks
#define NCMP  512             // 512 blocks * 8 warps = 4096 rows compacted

// Scratch (recomputed every launch; zero-init at load, our writes only -> always in-bounds)
__device__ __align__(16) float Pbuf[VOCAB * 2];
__device__ __align__(16) int   CIDX[BATCH * SEQ];
__device__ int                 CNT[BATCH];

// ---- K1: heterogeneous. Blocks <NPRE: P = emb @ W^T. Blocks >=NPRE: compact indices. ----
__global__ __launch_bounds__(256)
void k1_precompute_compact(const float* __restrict__ emb,
                           const float* __restrict__ W,
                           const int* __restrict__ x)
{
    const int warp = threadIdx.x >> 5;
    const int lane = threadIdx.x & 31;

    if (blockIdx.x < NPRE) {
        // ---- P GEMV: 8 lanes per row, 8 rows per warp ----
        const int warp_g = blockIdx.x * 8 + warp;
        const int sub = lane & 7;
        const int grp = lane >> 3;
        const int row_base = warp_g * 8;
        if (row_base >= VOCAB) return;

        const float4* emb4 = reinterpret_cast<const float4*>(emb);
        const float4* W4   = reinterpret_cast<const float4*>(W);

        float4 w0[4], w1[4];
        #pragma unroll
        for (int i = 0; i < 4; i++) {
            w0[i] = __ldg(&W4[sub + 8 * i]);
            w1[i] = __ldg(&W4[32 + sub + 8 * i]);
        }

        int rA = row_base + grp;
        int rB = row_base + 4 + grp;
        int cA = (rA < VOCAB) ? rA : VOCAB - 1;
        int cB = (rB < VOCAB) ? rB : VOCAB - 1;

        float4 eA[4], eB[4];
        #pragma unroll
        for (int i = 0; i < 4; i++) {
            eA[i] = __ldg(&emb4[cA * 32 + sub + 8 * i]);
            eB[i] = __ldg(&emb4[cB * 32 + sub + 8 * i]);
        }

        float dA0 = 0.f, dA1 = 0.f, dB0 = 0.f, dB1 = 0.f;
        #pragma unroll
        for (int i = 0; i < 4; i++) {
            dA0 += eA[i].x * w0[i].x + eA[i].y * w0[i].y + eA[i].z * w0[i].z + eA[i].w * w0[i].w;
            dA1 += eA[i].x * w1[i].x + eA[i].y * w1[i].y + eA[i].z * w1[i].z + eA[i].w * w1[i].w;
            dB0 += eB[i].x * w0[i].x + eB[i].y * w0[i].y + eB[i].z * w0[i].z + eB[i].w * w0[i].w;
            dB1 += eB[i].x * w1[i].x + eB[i].y * w1[i].y + eB[i].z * w1[i].z + eB[i].w * w1[i].w;
        }

        #pragma unroll
        for (int off = 4; off > 0; off >>= 1) {
            dA0 += __shfl_xor_sync(0xFFFFFFFFu, dA0, off);
            dA1 += __shfl_xor_sync(0xFFFFFFFFu, dA1, off);
            dB0 += __shfl_xor_sync(0xFFFFFFFFu, dB0, off);
            dB1 += __shfl_xor_sync(0xFFFFFFFFu, dB1, off);
        }

        if (sub == 0) {
            float2* P2 = reinterpret_cast<float2*>(Pbuf);
            if (rA < VOCAB) P2[rA] = make_float2(dA0, dA1);
            if (rB < VOCAB) P2[rB] = make_float2(dB0, dB1);
        }
    } else {
        // ---- Compaction: one warp per batch row (512 blocks * 8 warps = 4096 rows) ----
        const int row = (blockIdx.x - NPRE) * 8 + warp;
        const int* xr = x + row * SEQ;
        int base = 0;
        #pragma unroll
        for (int c = 0; c < 7; c++) {
            int s   = 32 * c + lane;
            int idx = (s < SEQ) ? __ldg(&xr[s]) : -1;
            bool valid = (idx >= 0);
            unsigned bm = __ballot_sync(0xFFFFFFFFu, valid);
            if (valid)
                CIDX[row * SEQ + base + __popc(bm & ((1u << lane) - 1u))] = idx;
            base += __popc(bm);
        }
        if (lane == 0) CNT[row] = base;     // >= 1 (column 0 always valid)
    }
}

// ---- K2: gather compacted indices from L2, reduce, write out. 2 warps per row. ----
__global__ __launch_bounds__(256)
void k2_gather(const float* __restrict__ bias,
               float* __restrict__ out)
{
    const int tid    = threadIdx.x;
    const int warp   = tid >> 5;            // 0..7
    const int lane   = tid & 31;
    const int warp_g = blockIdx.x * 8 + warp;
    const int row    = warp_g >> 1;         // 4 rows per block
    const int half   = warp_g & 1;

    const int* ci = CIDX + row * SEQ;
    const float2* P = reinterpret_cast<const float2*>(Pbuf);

    int cnt = __ldg(&CNT[row]);             // independent small load

    // Slots for this half-warp: i = lane + 32*half + 64*k, k=0..3 (covers up to 200).
    const int s0 = lane + 32 * half;
    // Unconditional idx loads (scratch always in-bounds; masked below). MLP high.
    int i0 = __ldg(&ci[s0]);
    int i1 = __ldg(&ci[s0 + 64]);
    int i2 = __ldg(&ci[s0 + 128]);
    int i3 = (s0 + 192 < SEQ) ? __ldg(&ci[s0 + 192]) : 0;

    // Clamp (stale scratch is in-bounds, but belt-and-braces) + gather.
    i0 = min(max(i0, 0), VOCAB - 1);
    i1 = min(max(i1, 0), VOCAB - 1);
    i2 = min(max(i2, 0), VOCAB - 1);
    i3 = min(max(i3, 0), VOCAB - 1);

    float2 p0 = __ldg(&P[i0]);
    float2 p1 = __ldg(&P[i1]);
    float2 p2 = __ldg(&P[i2]);
    float2 p3 = __ldg(&P[i3]);

    float m0 = (s0       < cnt) ? 1.f : 0.f;
    float m1 = (s0 + 64  < cnt) ? 1.f : 0.f;
    float m2 = (s0 + 128 < cnt) ? 1.f : 0.f;
    float m3 = (s0 + 192 < cnt) ? 1.f : 0.f;

    float a0 = m0 * p0.x + m1 * p1.x + m2 * p2.x + m3 * p3.x;
    float a1 = m0 * p0.y + m1 * p1.y + m2 * p2.y + m3 * p3.y;

    #pragma unroll
    for (int off = 16; off > 0; off >>= 1) {
        a0 += __shfl_xor_sync(0xFFFFFFFFu, a0, off);
        a1 += __shfl_xor_sync(0xFFFFFFFFu, a1, off);
    }

    __shared__ __align__(16) float2 part[8];
    __shared__ int scnt[4];
    if (lane == 0) {
        part[warp] = make_float2(a0, a1);
        if (half == 0) scnt[warp >> 1] = cnt;
    }
    __syncthreads();

    // 4 rows per block: thread t < 4 combines halves of row blockIdx.x*4 + t.
    if (tid < 4) {
        float2 h0 = part[2 * tid];
        float2 h1 = part[2 * tid + 1];
        float inv = 1.0f / (float)scnt[tid];     // cnt >= 1
        int r = blockIdx.x * 4 + tid;
        out[r * 2 + 0] = (h0.x + h1.x) * inv + bias[0];
        out[r * 2 + 1] = (h0.y + h1.y) * inv + bias[1];
    }
}

extern "C" void kernel_launch(void* const* d_in, const int* in_sizes, int n_in,
                              void* d_out, int out_size)
{
    const int* x     = (const int*)d_in[0];       // int32 [4096,200]
    const float* emb = (const float*)d_in[1];     // [100000,128]
    const float* W   = (const float*)d_in[2];     // [2,128]
    const float* b   = (const float*)d_in[3];     // [2]
    float* out       = (float*)d_out;             // [4096,2]

    k1_precompute_compact<<<NPRE + NCMP, 256>>>(emb, W, x);
    k2_gather<<<BATCH / 4, 256>>>(b, out);
}